// round 8
// baseline (speedup 1.0000x reference)
#include <cuda_runtime.h>
#include <math_constants.h>
#include <stdint.h>

#define KCODES 512
#define DDIM   64
#define NROW   65536
#define QELEMS 4194304
#define NBLK   148
#define NTHR   256            // 8 warps; reg budget 64K/256 = 255
#define MAXROWS 448           // max rows per block (14 rowsets x 32)

__device__ double   g_partial[NBLK];
__device__ unsigned g_count = 0;

// smem floats: sw2 32768 | sb 512 | mbb 4*448 | mbi 4*448 | sred 256 doubles
#define SMEM_BYTES (32768*4 + 512*4 + 4*448*4 + 4*448*4 + 256*8)   // 149504

// ---- f32x2 packed helpers (each lane rounds exactly like scalar __fmaf_rn) --
__device__ __forceinline__ unsigned long long pack2(float lo, float hi) {
    unsigned long long r;
    asm("mov.b64 %0, {%1, %2};" : "=l"(r) : "f"(lo), "f"(hi));
    return r;
}
__device__ __forceinline__ void unpack2(unsigned long long v, float& lo, float& hi) {
    asm("mov.b64 {%0, %1}, %2;" : "=f"(lo), "=f"(hi) : "l"(v));
}
__device__ __forceinline__ void fma2(unsigned long long& acc,
                                     unsigned long long a, unsigned long long b) {
    asm("fma.rn.f32x2 %0, %1, %2, %0;" : "+l"(acc) : "l"(a), "l"(b));
}

// ---------------------------------------------------------------------------
// Zero this block's encoding rows; enc base is only 4B-aligned
// (d_out+4+4*QELEMS) -> scalar fringes around a float4 interior.
// ---------------------------------------------------------------------------
__device__ __forceinline__ void zero_rows(float* __restrict__ enc,
                                          int row0, int nrows, int tid) {
    float* p = enc + (size_t)row0 * KCODES;
    int n = nrows * KCODES;
    uintptr_t a = (uintptr_t)p;
    int head = (int)((((a + 15) & ~(uintptr_t)15) - a) >> 2);   // 0..3
    if (tid < head) p[tid] = 0.0f;
    int n4 = (n - head) >> 2;
    int tail = (n - head) & 3;
    float4* v = (float4*)(p + head);
    float4 z = make_float4(0.f, 0.f, 0.f, 0.f);
    for (int i = tid; i < n4; i += NTHR) v[i] = z;
    if (tid >= 4 && tid - 4 < tail) p[head + 4 * n4 + (tid - 4)] = 0.0f;
}

// ---------------------------------------------------------------------------
// Fused kernel. Codebook stored PAIR-INTERLEAVED in smem:
//   sw2[p*128 + 2*d + s] = w[2p+s][d]   (p=pair, s=0/1)
// so one LDS.128 yields {u[d],v[d],u[d+1],v[d+1]} for codes (2p, 2p+1).
// Job = 1 warp x 32 rows (1/lane) x 128 codes (one k-quarter), FFMA2 body.
// ---------------------------------------------------------------------------
__global__ void __launch_bounds__(NTHR, 1) vq_fused(
    const float* __restrict__ x,
    const float* __restrict__ w,
    float* __restrict__ out,       // out[0] = loss
    float* __restrict__ qout,
    float* __restrict__ enc)
{
    extern __shared__ float sm[];
    float*  sw2  = sm;                         // [32768] pair-interleaved
    float*  sb   = sm + 32768;                 // [512] code norms
    float*  mbb  = sb + 512;                   // [4][448] partial best dist
    int*    mbi  = (int*)(mbb + 4 * 448);      // [4][448] partial best idx
    double* sred = (double*)(mbi + 4 * 448);   // [256]

    const int tid  = threadIdx.x;
    const int bid  = blockIdx.x;
    const int wid  = tid >> 5;
    const int lane = tid & 31;

    // Block -> contiguous 32-row rowsets: 136 blocks x 14, 12 blocks x 12
    const int cnt   = (bid < 136) ? 14 : 12;
    const int rs0   = (bid < 136) ? bid * 14 : 1904 + (bid - 136) * 12;
    const int row0  = rs0 * 32;
    const int nrows = cnt * 32;
    const int njobs = cnt * 4;            // 56 or 48; /8 warps = 7 or 6 exact

    // Stage codebook into pair-interleaved smem
    {
        const float4* w4 = (const float4*)w;
        for (int i = tid; i < 8192; i += NTHR) {
            float4 v = w4[i];
            int k = i >> 4, d0 = (i & 15) << 2;
            float* dst = sw2 + (k >> 1) * 128 + (k & 1);
            dst[(d0 + 0) * 2] = v.x;
            dst[(d0 + 1) * 2] = v.y;
            dst[(d0 + 2) * 2] = v.z;
            dst[(d0 + 3) * 2] = v.w;
        }
    }

    // Zero-fill exactly this block's enc rows (drains under the FFMA loop)
    zero_rows(enc, row0, nrows, tid);

    __syncthreads();

    // Codebook norms — identical rounding chain to reference
    for (int k = tid; k < KCODES; k += NTHR) {
        const float* pk = sw2 + (k >> 1) * 128 + (k & 1);
        float acc = 0.0f;
        #pragma unroll
        for (int d = 0; d < DDIM; d++)
            acc = __fadd_rn(acc, __fmul_rn(pk[2 * d], pk[2 * d]));
        sb[k] = acc;
    }
    __syncthreads();

    // ---------------- Main phase: quarter-jobs ----------------------------
    #pragma unroll 1
    for (int i = 0; i < 7; i++) {
        int jj = wid + 8 * i;
        if (jj >= njobs) break;
        const int rsl = jj >> 2;            // local rowset 0..cnt-1
        const int q   = jj & 3;             // code quarter 0..3
        const int n   = row0 + rsl * 32 + lane;
        const int b   = n >> 10, hw = n & 1023;
        const float* p = x + (size_t)b * 65536 + hw;

        // Load row, pack x[d] into both f32x2 lanes; scalar-sequential a.
        unsigned long long xp[DDIM];
        float a = 0.0f;
        #pragma unroll
        for (int d = 0; d < DDIM; d++) {
            float xv = p[d * 1024];
            xp[d] = pack2(xv, xv);
            a = __fadd_rn(a, __fmul_rn(xv, xv));
        }

        float best = CUDART_INF_F;
        int   bi   = 0;

        // 32 groups of 4 codes: 128 FFMA2 + 64 LDS.128 per group.
        #pragma unroll 1
        for (int g = 0; g < 32; g++) {
            const int kp0 = q * 64 + 2 * g;             // pair ids kp0, kp0+1
            const ulonglong2* pr0 = (const ulonglong2*)(sw2 + kp0 * 128);
            const ulonglong2* pr1 = (const ulonglong2*)(sw2 + kp0 * 128 + 128);
            unsigned long long acc0 = 0ull, acc1 = 0ull;
            #pragma unroll
            for (int j = 0; j < 32; j++) {
                ulonglong2 A = pr0[j];    // {u(d),v(d)} , {u(d+1),v(d+1)}
                ulonglong2 B = pr1[j];
                fma2(acc0, xp[2*j],     A.x);
                fma2(acc0, xp[2*j + 1], A.y);
                fma2(acc1, xp[2*j],     B.x);
                fma2(acc1, xp[2*j + 1], B.y);
            }
            float ma0, mb0, ma1, mb1;
            unpack2(acc0, ma0, mb0);
            unpack2(acc1, ma1, mb1);
            const int k0 = 2 * kp0;                     // codes k0..k0+3
            // d = fl( fl(a + b) - fl(2*m) ) — exact reference rounding
            float d0 = __fsub_rn(__fadd_rn(a, sb[k0    ]), __fmul_rn(2.0f, ma0));
            float d1 = __fsub_rn(__fadd_rn(a, sb[k0 + 1]), __fmul_rn(2.0f, mb0));
            float d2 = __fsub_rn(__fadd_rn(a, sb[k0 + 2]), __fmul_rn(2.0f, ma1));
            float d3 = __fsub_rn(__fadd_rn(a, sb[k0 + 3]), __fmul_rn(2.0f, mb1));
            if (d0 < best) { best = d0; bi = k0; }      // strict <: first index
            if (d1 < best) { best = d1; bi = k0 + 1; }
            if (d2 < best) { best = d2; bi = k0 + 2; }
            if (d3 < best) { best = d3; bi = k0 + 3; }
        }

        // Store partials; [q][row] layout -> consecutive lanes, no conflicts
        int r = rsl * 32 + lane;
        mbb[q * MAXROWS + r] = best;
        mbi[q * MAXROWS + r] = bi;
    }
    __syncthreads();

    // ---------------- Epilogue: merge quarters + outputs -------------------
    double ls = 0.0;
    for (int rl = tid; rl < nrows; rl += NTHR) {
        // Ascending-q merge with strict < == global first-index argmin
        float best = CUDART_INF_F; int bi = 0;
        #pragma unroll
        for (int q = 0; q < 4; q++) {
            float d = mbb[q * MAXROWS + rl];
            int   k = mbi[q * MAXROWS + rl];
            if (d < best) { best = d; bi = k; }
        }
        const int n = row0 + rl;
        const int b = n >> 10, hw = n & 1023;
        const float* p  = x    + (size_t)b * 65536 + hw;
        float*       qp = qout + (size_t)b * 65536 + hw;
        const float* wq = sw2 + (bi >> 1) * 128 + (bi & 1);
        #pragma unroll
        for (int d = 0; d < DDIM; d++) {
            float xv   = p[d * 1024];
            float diff = __fsub_rn(wq[2 * d], xv);
            qp[d * 1024] = __fadd_rn(xv, diff);     // straight-through
            ls += (double)__fmul_rn(diff, diff);
        }
        enc[(size_t)n * KCODES + bi] = 1.0f;
    }

    // Deterministic block-level loss reduction (fixed tree)
    sred[tid] = ls;
    __syncthreads();
    for (int s = NTHR / 2; s > 0; s >>= 1) {
        if (tid < s) sred[tid] += sred[tid + s];
        __syncthreads();
    }

    // Last-block final reduce (fence+atomic; deterministic fixed-order sum)
    __shared__ int isLast;
    if (tid == 0) {
        g_partial[bid] = sred[0];
        __threadfence();
        unsigned old = atomicAdd(&g_count, 1u);
        isLast = (old == NBLK - 1u) ? 1 : 0;
    }
    __syncthreads();
    if (isLast) {
        sred[tid] = (tid < NBLK) ? g_partial[tid] : 0.0;
        __syncthreads();
        for (int s = NTHR / 2; s > 0; s >>= 1) {
            if (tid < s) sred[tid] += sred[tid + s];
            __syncthreads();
        }
        if (tid == 0) {
            float m = (float)(sred[0] / (double)QELEMS);
            out[0] = __fadd_rn(m, __fmul_rn(0.25f, m));  // z_q + 0.25*z_e
            g_count = 0;                                 // reset for replay
        }
    }
}

// ---------------------------------------------------------------------------
extern "C" void kernel_launch(void* const* d_in, const int* in_sizes, int n_in,
                              void* d_out, int out_size) {
    const float* x = (const float*)d_in[0];   // [64,64,32,32] fp32
    const float* w = (const float*)d_in[1];   // [512,64] fp32
    float* out  = (float*)d_out;
    float* qout = out + 1;                    // [4194304] (4B-aligned only)
    float* enc  = out + 1 + QELEMS;           // [65536*512] (4B-aligned only)

    cudaFuncSetAttribute(vq_fused, cudaFuncAttributeMaxDynamicSharedMemorySize,
                         SMEM_BYTES);

    vq_fused<<<NBLK, NTHR, SMEM_BYTES>>>(x, w, out, qout, enc);
}